// round 9
// baseline (speedup 1.0000x reference)
#include <cuda_runtime.h>
#include <cstdint>

#define DEV_INLINE __device__ __forceinline__

static constexpr int M = 2048, K = 4096, N = 11008;
static constexpr int BM = 128, BN = 128, BK = 64;
static constexpr int STAGES = 4;
static constexpr int K_ITERS = K / BK;              // 64
static constexpr int ASTR = 80;                     // padded smem row stride
static constexpr int A_TILE = BM * ASTR;            // 10240
static constexpr int B_TILE = BN * ASTR;            // 10240
static constexpr int STAGE_BYTES = A_TILE + B_TILE; // 20480
static constexpr int SMEM_TOTAL = STAGES * STAGE_BYTES;  // 81920

__device__ int8_t g_xq[(size_t)M * K];      // quantized activations
__device__ int8_t g_wt[(size_t)N * K];      // W narrowed + transposed to [N, K] s8
__device__ unsigned g_maxbits;              // max|x| as float bits

// ============================ PTX helpers ============================

DEV_INLINE uint32_t smem_u32(const void* p) {
  uint32_t a;
  asm("{ .reg .u64 t; cvta.to.shared.u64 t, %1; cvt.u32.u64 %0, t; }"
      : "=r"(a) : "l"(p));
  return a;
}

DEV_INLINE void cp16(uint32_t dst, const void* src) {
  asm volatile("cp.async.cg.shared.global [%0], [%1], 16;"
               :: "r"(dst), "l"(src));
}
#define CP_COMMIT() asm volatile("cp.async.commit_group;" ::: "memory")
#define CP_WAIT_2() asm volatile("cp.async.wait_group 2;" ::: "memory")

DEV_INLINE void mma_s8(int& c0, int& c1, int& c2, int& c3,
                       uint32_t a0, uint32_t a1, uint32_t a2, uint32_t a3,
                       uint32_t b0, uint32_t b1) {
  asm volatile(
      "mma.sync.aligned.m16n8k32.row.col.s32.s8.s8.s32 "
      "{%0,%1,%2,%3}, {%4,%5,%6,%7}, {%8,%9}, {%0,%1,%2,%3};"
      : "+r"(c0), "+r"(c1), "+r"(c2), "+r"(c3)
      : "r"(a0), "r"(a1), "r"(a2), "r"(a3), "r"(b0), "r"(b1));
}

// ============================ pre-pass kernels ============================

__global__ void k_zero() { g_maxbits = 0u; }

__global__ void __launch_bounds__(256) k_maxabs(const float4* __restrict__ x) {
  const int n4 = M * K / 4;
  float m = 0.0f;
  for (int i = blockIdx.x * blockDim.x + threadIdx.x; i < n4;
       i += gridDim.x * blockDim.x) {
    float4 v = x[i];
    m = fmaxf(m, fmaxf(fmaxf(fabsf(v.x), fabsf(v.y)),
                       fmaxf(fabsf(v.z), fabsf(v.w))));
  }
  #pragma unroll
  for (int o = 16; o > 0; o >>= 1) m = fmaxf(m, __shfl_xor_sync(0xFFFFFFFFu, m, o));
  __shared__ float red[8];
  if ((threadIdx.x & 31) == 0) red[threadIdx.x >> 5] = m;
  __syncthreads();
  if (threadIdx.x == 0) {
    float t = red[0];
    #pragma unroll
    for (int j = 1; j < 8; ++j) t = fmaxf(t, red[j]);
    atomicMax(&g_maxbits, __float_as_uint(t));
  }
}

__global__ void __launch_bounds__(256) k_quant(const float4* __restrict__ x) {
  const float scale = __uint_as_float(g_maxbits) * (1.0f / 128.0f);
  const int n4 = M * K / 4;
  char4* __restrict__ out = (char4*)g_xq;
  for (int i = blockIdx.x * blockDim.x + threadIdx.x; i < n4;
       i += gridDim.x * blockDim.x) {
    float4 v = x[i];
    int a = __float2int_rn(__fdiv_rn(v.x, scale));
    int b = __float2int_rn(__fdiv_rn(v.y, scale));
    int c = __float2int_rn(__fdiv_rn(v.z, scale));
    int d = __float2int_rn(__fdiv_rn(v.w, scale));
    a = max(-128, min(127, a)); b = max(-128, min(127, b));
    c = max(-128, min(127, c)); d = max(-128, min(127, d));
    out[i] = make_char4((signed char)a, (signed char)b,
                        (signed char)c, (signed char)d);
  }
}

// W arrives as INT32 [K][N] (harness promotes int8 -> int32; harness type
// palette has no int8). Narrow to s8 and transpose to Wt[N][K] int8.
__global__ void __launch_bounds__(256) k_transpose(const int* __restrict__ W32) {
  __shared__ int8_t tile[64][68];   // [k_local][n_local], padded rows
  const int k0 = blockIdx.x * 64;
  const int n0 = blockIdx.y * 64;
  const int t = threadIdx.x;

  // load: 64 rows (k) x 64 int32 (n); consecutive threads -> consecutive
  // addresses, coalesced. Narrow to s8 on the fly.
  #pragma unroll
  for (int it = 0; it < 16; ++it) {
    int idx = t + it * 256;          // 0..4095
    int r = idx >> 6;                // k row 0..63
    int c = idx & 63;                // n col 0..63
    tile[r][c] = (int8_t)W32[(size_t)(k0 + r) * N + n0 + c];
  }
  __syncthreads();

  // store: for each n, assemble 4 k-bytes into a word; coalesced 4B stores
  #pragma unroll
  for (int it = 0; it < 4; ++it) {
    int idx = t + it * 256;          // 0..1023 words
    int n = idx >> 4;                // 0..63
    int kk = (idx & 15) << 2;        // k byte 0..60
    uint32_t w = (uint32_t)(uint8_t)tile[kk + 0][n]
               | ((uint32_t)(uint8_t)tile[kk + 1][n] << 8)
               | ((uint32_t)(uint8_t)tile[kk + 2][n] << 16)
               | ((uint32_t)(uint8_t)tile[kk + 3][n] << 24);
    *(uint32_t*)(g_wt + (size_t)(n0 + n) * K + k0 + kk) = w;
  }
}

// ============================ GEMM kernel ============================

DEV_INLINE void load_stage(uint32_t stA, int m0, int n0, int k0, int tid) {
  const uint32_t stB = stA + A_TILE;
  #pragma unroll
  for (int p = 0; p < 2; ++p) {
    int t2 = tid + p * 256;
    int row = t2 >> 2;
    int ch = (t2 & 3) << 4;
    cp16(stA + row * ASTR + ch, g_xq + (size_t)(m0 + row) * K + k0 + ch);
  }
  #pragma unroll
  for (int p = 0; p < 2; ++p) {
    int t2 = tid + p * 256;
    int row = t2 >> 2;
    int ch = (t2 & 3) << 4;
    cp16(stB + row * ASTR + ch, g_wt + (size_t)(n0 + row) * K + k0 + ch);
  }
}

__global__ void __launch_bounds__(256, 2)
qlinear_gemm(const float* __restrict__ bias, float* __restrict__ out) {
  extern __shared__ __align__(16) char smem[];
  const uint32_t sbase = smem_u32(smem);
  const int tid = threadIdx.x;
  const int wid = tid >> 5;
  const int lane = tid & 31;
  const int wm = wid & 1;        // 2 warps along m
  const int wn = wid >> 1;       // 4 warps along n
  const int m0 = blockIdx.x * BM;
  const int n0 = blockIdx.y * BN;

  // mma fragment coordinates (PTX ISA m16n8k32.row.col):
  //  A: a0 = [row g][k tg*4..+3], a1 = row+8, a2 = k+16, a3 = both
  //  B: b0 = [n g][k tg*4..+3],  b1 = k+16
  const int gr = lane >> 2;      // 0..7
  const int tg = lane & 3;       // 0..3

  int c[4][4][4];
  #pragma unroll
  for (int i = 0; i < 4; ++i)
    #pragma unroll
    for (int j = 0; j < 4; ++j)
      #pragma unroll
      for (int q = 0; q < 4; ++q) c[i][j][q] = 0;

  // prologue: stages 0..2
  #pragma unroll
  for (int j = 0; j < STAGES - 1; ++j) {
    load_stage(sbase + j * STAGE_BYTES, m0, n0, j * BK, tid);
    CP_COMMIT();
  }

  for (int i = 0; i < K_ITERS; ++i) {
    CP_WAIT_2();
    __syncthreads();
    const char* stA = smem + (i & 3) * STAGE_BYTES;
    const char* stB = stA + A_TILE;

    #pragma unroll
    for (int s = 0; s < 2; ++s) {            // two k32 steps per stage
      const int kb = s * 32;
      uint32_t a[4][4], bb[4][2];
      #pragma unroll
      for (int mt = 0; mt < 4; ++mt) {
        const char* ap = stA + (wm * 64 + mt * 16 + gr) * ASTR + kb + tg * 4;
        a[mt][0] = *(const uint32_t*)(ap);
        a[mt][1] = *(const uint32_t*)(ap + 8 * ASTR);
        a[mt][2] = *(const uint32_t*)(ap + 16);
        a[mt][3] = *(const uint32_t*)(ap + 8 * ASTR + 16);
      }
      #pragma unroll
      for (int nt = 0; nt < 4; ++nt) {
        const char* bp = stB + (wn * 32 + nt * 8 + gr) * ASTR + kb + tg * 4;
        bb[nt][0] = *(const uint32_t*)(bp);
        bb[nt][1] = *(const uint32_t*)(bp + 16);
      }
      #pragma unroll
      for (int mt = 0; mt < 4; ++mt)
        #pragma unroll
        for (int nt = 0; nt < 4; ++nt)
          mma_s8(c[mt][nt][0], c[mt][nt][1], c[mt][nt][2], c[mt][nt][3],
                 a[mt][0], a[mt][1], a[mt][2], a[mt][3],
                 bb[nt][0], bb[nt][1]);
    }

    const int nl = i + STAGES - 1;
    if (nl < K_ITERS)
      load_stage(sbase + (nl & 3) * STAGE_BYTES, m0, n0, nl * BK, tid);
    CP_COMMIT();   // uniform group counting (possibly empty group)
  }

  // epilogue: s32 accum fragment: c0,c1 -> (row g, col tg*2+{0,1});
  // c2,c3 -> row g+8.
  const float s = __uint_as_float(g_maxbits) * (1.0f / 128.0f) * 0.0123f;
  const int gc = tg << 1;
  #pragma unroll
  for (int mt = 0; mt < 4; ++mt) {
    const int m = m0 + wm * 64 + mt * 16 + gr;
    float* __restrict__ row0 = out + (size_t)m * N;
    float* __restrict__ row1 = row0 + (size_t)8 * N;
    #pragma unroll
    for (int nt = 0; nt < 4; ++nt) {
      const int col = n0 + wn * 32 + nt * 8 + gc;
      const float2 bv = *(const float2*)(bias + col);
      float2 v0, v1;
      v0.x = fmaf((float)c[mt][nt][0], s, bv.x);
      v0.y = fmaf((float)c[mt][nt][1], s, bv.y);
      v1.x = fmaf((float)c[mt][nt][2], s, bv.x);
      v1.y = fmaf((float)c[mt][nt][3], s, bv.y);
      *(float2*)(row0 + col) = v0;
      *(float2*)(row1 + col) = v1;
    }
  }
}

// ============================ launch ============================

extern "C" void kernel_launch(void* const* d_in, const int* in_sizes, int n_in,
                              void* d_out, int out_size) {
  const float* x    = (const float*)d_in[0];
  const int*   W32  = (const int*)d_in[1];    // int8 weights promoted to int32
  const float* bias = (const float*)d_in[2];
  float* out = (float*)d_out;

  k_zero<<<1, 1>>>();
  k_maxabs<<<1024, 256>>>((const float4*)x);
  k_quant<<<2048, 256>>>((const float4*)x);
  {
    dim3 tg(K / 64, N / 64);    // 64 x 172
    k_transpose<<<tg, 256>>>(W32);
  }

  cudaFuncSetAttribute(qlinear_gemm,
                       cudaFuncAttributeMaxDynamicSharedMemorySize, SMEM_TOTAL);
  dim3 grid(M / BM, N / BN);    // 16 x 86; m fastest -> B-stripe L2 reuse
  qlinear_gemm<<<grid, 256, SMEM_TOTAL>>>(bias, out);
}

// round 10
// speedup vs baseline: 1.1384x; 1.1384x over previous
#include <cuda_runtime.h>
#include <cstdint>

#define DEV_INLINE __device__ __forceinline__

static constexpr int M = 2048, K = 4096, N = 11008;
static constexpr int BM = 128, BN = 128, BK = 64;
static constexpr int STAGES = 4;
static constexpr int K_ITERS = K / BK;              // 64
static constexpr int ASTR = 80;                     // padded smem row stride
static constexpr int A_TILE = BM * ASTR;            // 10240
static constexpr int B_TILE = BN * ASTR;            // 10240
static constexpr int STAGE_BYTES = A_TILE + B_TILE; // 20480
static constexpr int SMEM_TOTAL = STAGES * STAGE_BYTES;  // 81920
static constexpr int MAX_BLOCKS = 1024;

__device__ int8_t g_xq[(size_t)M * K];      // quantized activations
__device__ int8_t g_wt[(size_t)N * K];      // W narrowed + transposed to [N, K] s8
__device__ float g_partial[MAX_BLOCKS];     // per-block |x| maxima
__device__ float g_scale;                   // max|x| / 128

// ============================ PTX helpers ============================

DEV_INLINE uint32_t smem_u32(const void* p) {
  uint32_t a;
  asm("{ .reg .u64 t; cvta.to.shared.u64 t, %1; cvt.u32.u64 %0, t; }"
      : "=r"(a) : "l"(p));
  return a;
}

DEV_INLINE void cp16(uint32_t dst, const void* src) {
  asm volatile("cp.async.cg.shared.global [%0], [%1], 16;"
               :: "r"(dst), "l"(src));
}
#define CP_COMMIT() asm volatile("cp.async.commit_group;" ::: "memory")
#define CP_WAIT_2() asm volatile("cp.async.wait_group 2;" ::: "memory")

DEV_INLINE void ldsm_x4(uint32_t& r0, uint32_t& r1, uint32_t& r2, uint32_t& r3,
                        uint32_t addr) {
  asm volatile("ldmatrix.sync.aligned.m8n8.x4.shared.b16 {%0,%1,%2,%3}, [%4];"
               : "=r"(r0), "=r"(r1), "=r"(r2), "=r"(r3) : "r"(addr)
               : "memory");
}

DEV_INLINE void mma_s8(int& c0, int& c1, int& c2, int& c3,
                       uint32_t a0, uint32_t a1, uint32_t a2, uint32_t a3,
                       uint32_t b0, uint32_t b1) {
  asm volatile(
      "mma.sync.aligned.m16n8k32.row.col.s32.s8.s8.s32 "
      "{%0,%1,%2,%3}, {%4,%5,%6,%7}, {%8,%9}, {%0,%1,%2,%3};"
      : "+r"(c0), "+r"(c1), "+r"(c2), "+r"(c3)
      : "r"(a0), "r"(a1), "r"(a2), "r"(a3), "r"(b0), "r"(b1));
}

// ============================ pre-pass kernels ============================

// Per-block max -> g_partial[blockIdx]. No atomics, no zeroing needed:
// every slot is rewritten every call (deterministic).
__global__ void __launch_bounds__(256) k_maxabs(const float4* __restrict__ x) {
  const int n4 = M * K / 4;
  float m = 0.0f;
  for (int i = blockIdx.x * blockDim.x + threadIdx.x; i < n4;
       i += gridDim.x * blockDim.x) {
    float4 v = x[i];
    m = fmaxf(m, fmaxf(fmaxf(fabsf(v.x), fabsf(v.y)),
                       fmaxf(fabsf(v.z), fabsf(v.w))));
  }
  #pragma unroll
  for (int o = 16; o > 0; o >>= 1) m = fmaxf(m, __shfl_xor_sync(0xFFFFFFFFu, m, o));
  __shared__ float red[8];
  if ((threadIdx.x & 31) == 0) red[threadIdx.x >> 5] = m;
  __syncthreads();
  if (threadIdx.x == 0) {
    float t = red[0];
    #pragma unroll
    for (int j = 1; j < 8; ++j) t = fmaxf(t, red[j]);
    g_partial[blockIdx.x] = t;
  }
}

__global__ void __launch_bounds__(256) k_quant(const float4* __restrict__ x) {
  // every block re-reduces the 1024 partials (cheap, L2-resident)
  __shared__ float red[8];
  __shared__ float bcast;
  {
    float m = 0.0f;
    #pragma unroll
    for (int j = 0; j < MAX_BLOCKS / 256; ++j)
      m = fmaxf(m, g_partial[threadIdx.x + j * 256]);
    #pragma unroll
    for (int o = 16; o > 0; o >>= 1)
      m = fmaxf(m, __shfl_xor_sync(0xFFFFFFFFu, m, o));
    if ((threadIdx.x & 31) == 0) red[threadIdx.x >> 5] = m;
    __syncthreads();
    if (threadIdx.x == 0) {
      float t = red[0];
      #pragma unroll
      for (int j = 1; j < 8; ++j) t = fmaxf(t, red[j]);
      bcast = t;
      if (blockIdx.x == 0) g_scale = t * (1.0f / 128.0f);
    }
    __syncthreads();
  }
  const float scale = bcast * (1.0f / 128.0f);
  const int n4 = M * K / 4;
  char4* __restrict__ out = (char4*)g_xq;
  for (int i = blockIdx.x * blockDim.x + threadIdx.x; i < n4;
       i += gridDim.x * blockDim.x) {
    float4 v = x[i];
    int a = __float2int_rn(__fdiv_rn(v.x, scale));
    int b = __float2int_rn(__fdiv_rn(v.y, scale));
    int c = __float2int_rn(__fdiv_rn(v.z, scale));
    int d = __float2int_rn(__fdiv_rn(v.w, scale));
    a = max(-128, min(127, a)); b = max(-128, min(127, b));
    c = max(-128, min(127, c)); d = max(-128, min(127, d));
    out[i] = make_char4((signed char)a, (signed char)b,
                        (signed char)c, (signed char)d);
  }
}

// W arrives as INT32 [K][N] (harness promotes int8 -> int32).
// Narrow to s8 and transpose to Wt[N][K] int8. 16B vectorized loads.
__global__ void __launch_bounds__(256) k_transpose(const int4* __restrict__ W32) {
  __shared__ int8_t tile[64][68];   // [k_local][n_local], padded rows
  const int k0 = blockIdx.x * 64;
  const int n0 = blockIdx.y * 64;
  const int t = threadIdx.x;
  const int Nv = N / 4;             // int4 stride per k-row

  // load: 64 rows (k) x 16 int4 (n); coalesced 16B loads, narrow to s8
  #pragma unroll
  for (int it = 0; it < 4; ++it) {
    int idx = t + it * 256;          // 0..1023
    int r = idx >> 4;                // k row 0..63
    int cv = idx & 15;               // int4 col 0..15 (n offset = cv*4)
    int4 v = W32[(size_t)(k0 + r) * Nv + (n0 >> 2) + cv];
    uint32_t w = (uint32_t)(uint8_t)(int8_t)v.x
               | ((uint32_t)(uint8_t)(int8_t)v.y << 8)
               | ((uint32_t)(uint8_t)(int8_t)v.z << 16)
               | ((uint32_t)(uint8_t)(int8_t)v.w << 24);
    *(uint32_t*)&tile[r][cv * 4] = w;
  }
  __syncthreads();

  // store: for each n, assemble 4 k-bytes into a word; coalesced 4B stores
  #pragma unroll
  for (int it = 0; it < 4; ++it) {
    int idx = t + it * 256;          // 0..1023 words
    int n = idx >> 4;                // 0..63
    int kk = (idx & 15) << 2;        // k byte 0..60
    uint32_t w = (uint32_t)(uint8_t)tile[kk + 0][n]
               | ((uint32_t)(uint8_t)tile[kk + 1][n] << 8)
               | ((uint32_t)(uint8_t)tile[kk + 2][n] << 16)
               | ((uint32_t)(uint8_t)tile[kk + 3][n] << 24);
    *(uint32_t*)(g_wt + (size_t)(n0 + n) * K + k0 + kk) = w;
  }
}

// ============================ GEMM kernel ============================

DEV_INLINE void load_stage(uint32_t stA, int m0, int n0, int k0, int tid) {
  const uint32_t stB = stA + A_TILE;
  #pragma unroll
  for (int p = 0; p < 2; ++p) {
    int t2 = tid + p * 256;
    int row = t2 >> 2;
    int ch = (t2 & 3) << 4;
    cp16(stA + row * ASTR + ch, g_xq + (size_t)(m0 + row) * K + k0 + ch);
  }
  #pragma unroll
  for (int p = 0; p < 2; ++p) {
    int t2 = tid + p * 256;
    int row = t2 >> 2;
    int ch = (t2 & 3) << 4;
    cp16(stB + row * ASTR + ch, g_wt + (size_t)(n0 + row) * K + k0 + ch);
  }
}

__global__ void __launch_bounds__(256, 2)
qlinear_gemm(const float* __restrict__ bias, float* __restrict__ out) {
  extern __shared__ __align__(16) char smem[];
  const uint32_t sbase = smem_u32(smem);
  const int tid = threadIdx.x;
  const int wid = tid >> 5;
  const int lane = tid & 31;
  const int wm = wid & 1;        // 2 warps along m
  const int wn = wid >> 1;       // 4 warps along n
  const int m0 = blockIdx.x * BM;
  const int n0 = blockIdx.y * BN;

  // ldmatrix lane roles (mapping proven equivalent to direct fragment
  // loads by R7/R8 identical-output evidence):
  const int row_in = lane & 7;
  const int b = lane >> 3;
  const int a_row = wm * 64 + (b & 1) * 8 + row_in;   // + mt*16
  const int a_coff = (b >> 1) * 16;                   // + kb
  const int b_row = wn * 32 + (b >> 1) * 8 + row_in;  // + p*16
  const int b_coff = (b & 1) * 16;                    // + kb

  int c[4][4][4];
  #pragma unroll
  for (int i = 0; i < 4; ++i)
    #pragma unroll
    for (int j = 0; j < 4; ++j)
      #pragma unroll
      for (int q = 0; q < 4; ++q) c[i][j][q] = 0;

  // prologue: stages 0..2
  #pragma unroll
  for (int j = 0; j < STAGES - 1; ++j) {
    load_stage(sbase + j * STAGE_BYTES, m0, n0, j * BK, tid);
    CP_COMMIT();
  }

  for (int i = 0; i < K_ITERS; ++i) {
    CP_WAIT_2();
    __syncthreads();
    const uint32_t stA = sbase + (i & 3) * STAGE_BYTES;
    const uint32_t stB = stA + A_TILE;

    #pragma unroll
    for (int s = 0; s < 2; ++s) {            // two k32 steps per stage
      const int kb = s * 32;
      uint32_t a[4][4], bb[4][2];
      #pragma unroll
      for (int mt = 0; mt < 4; ++mt)
        ldsm_x4(a[mt][0], a[mt][1], a[mt][2], a[mt][3],
                stA + (a_row + mt * 16) * ASTR + kb + a_coff);
      #pragma unroll
      for (int p = 0; p < 2; ++p) {          // each x4 covers 2 n-tiles
        uint32_t r0, r1, r2, r3;
        ldsm_x4(r0, r1, r2, r3,
                stB + (b_row + p * 16) * ASTR + kb + b_coff);
        bb[2 * p][0] = r0; bb[2 * p][1] = r1;
        bb[2 * p + 1][0] = r2; bb[2 * p + 1][1] = r3;
      }
      #pragma unroll
      for (int mt = 0; mt < 4; ++mt)
        #pragma unroll
        for (int nt = 0; nt < 4; ++nt)
          mma_s8(c[mt][nt][0], c[mt][nt][1], c[mt][nt][2], c[mt][nt][3],
                 a[mt][0], a[mt][1], a[mt][2], a[mt][3],
                 bb[nt][0], bb[nt][1]);
    }

    const int nl = i + STAGES - 1;
    if (nl < K_ITERS)
      load_stage(sbase + (nl & 3) * STAGE_BYTES, m0, n0, nl * BK, tid);
    CP_COMMIT();   // uniform group counting (possibly empty group)
  }

  // epilogue: s32 accum fragment: c0,c1 -> (row g, col tg*2+{0,1});
  // c2,c3 -> row g+8.
  const float s = g_scale * 0.0123f;
  const int gr = lane >> 2;
  const int gc = (lane & 3) << 1;
  #pragma unroll
  for (int mt = 0; mt < 4; ++mt) {
    const int m = m0 + wm * 64 + mt * 16 + gr;
    float* __restrict__ row0 = out + (size_t)m * N;
    float* __restrict__ row1 = row0 + (size_t)8 * N;
    #pragma unroll
    for (int nt = 0; nt < 4; ++nt) {
      const int col = n0 + wn * 32 + nt * 8 + gc;
      const float2 bv = *(const float2*)(bias + col);
      float2 v0, v1;
      v0.x = fmaf((float)c[mt][nt][0], s, bv.x);
      v0.y = fmaf((float)c[mt][nt][1], s, bv.y);
      v1.x = fmaf((float)c[mt][nt][2], s, bv.x);
      v1.y = fmaf((float)c[mt][nt][3], s, bv.y);
      *(float2*)(row0 + col) = v0;
      *(float2*)(row1 + col) = v1;
    }
  }
}

// ============================ launch ============================

extern "C" void kernel_launch(void* const* d_in, const int* in_sizes, int n_in,
                              void* d_out, int out_size) {
  const float* x    = (const float*)d_in[0];
  const int*   W32  = (const int*)d_in[1];    // int8 weights promoted to int32
  const float* bias = (const float*)d_in[2];
  float* out = (float*)d_out;

  k_maxabs<<<MAX_BLOCKS, 256>>>((const float4*)x);
  k_quant<<<2048, 256>>>((const float4*)x);
  {
    dim3 tg(K / 64, N / 64);    // 64 x 172
    k_transpose<<<tg, 256>>>((const int4*)W32);
  }

  cudaFuncSetAttribute(qlinear_gemm,
                       cudaFuncAttributeMaxDynamicSharedMemorySize, SMEM_TOTAL);
  dim3 grid(M / BM, N / BN);    // 16 x 86; m fastest -> B-stripe L2 reuse
  qlinear_gemm<<<grid, 256, SMEM_TOTAL>>>(bias, out);
}

// round 11
// speedup vs baseline: 1.2385x; 1.0879x over previous
#include <cuda_runtime.h>
#include <cstdint>

#define DEV_INLINE __device__ __forceinline__

static constexpr int M = 2048, K = 4096, N = 11008;
static constexpr int BM = 128, BN = 256, BK = 128;
static constexpr int STAGES = 3;
static constexpr int K_ITERS = K / BK;              // 32
static constexpr int ASTR = 144;                    // 128B row + 16B pad (conflict-free)
static constexpr int A_TILE = BM * ASTR;            // 18432
static constexpr int B_TILE = BN * ASTR;            // 36864
static constexpr int STAGE_BYTES = A_TILE + B_TILE; // 55296
static constexpr int SMEM_TOTAL = STAGES * STAGE_BYTES;  // 165888
static constexpr int MAX_BLOCKS = 1024;

__device__ int8_t g_xq[(size_t)M * K];      // quantized activations
__device__ int8_t g_wt[(size_t)N * K];      // W narrowed + transposed to [N, K] s8
__device__ float g_partial[MAX_BLOCKS];     // per-block |x| maxima
__device__ float g_scale;                   // max|x| / 128

// ============================ PTX helpers ============================

DEV_INLINE uint32_t smem_u32(const void* p) {
  uint32_t a;
  asm("{ .reg .u64 t; cvta.to.shared.u64 t, %1; cvt.u32.u64 %0, t; }"
      : "=r"(a) : "l"(p));
  return a;
}

DEV_INLINE void cp16(uint32_t dst, const void* src) {
  asm volatile("cp.async.cg.shared.global [%0], [%1], 16;"
               :: "r"(dst), "l"(src));
}
#define CP_COMMIT() asm volatile("cp.async.commit_group;" ::: "memory")
#define CP_WAIT_1() asm volatile("cp.async.wait_group 1;" ::: "memory")

// Non-volatile, no clobber: lets nvcc/ptxas software-pipeline ldsm across
// mma phases. Safety evidence: R7 (this form) produced bit-identical output
// to R8's plain-load version. __syncthreads() provides the stage ordering.
DEV_INLINE void ldsm_x4(uint32_t& r0, uint32_t& r1, uint32_t& r2, uint32_t& r3,
                        uint32_t addr) {
  asm("ldmatrix.sync.aligned.m8n8.x4.shared.b16 {%0,%1,%2,%3}, [%4];"
      : "=r"(r0), "=r"(r1), "=r"(r2), "=r"(r3) : "r"(addr));
}

DEV_INLINE void mma_s8(int& c0, int& c1, int& c2, int& c3,
                       uint32_t a0, uint32_t a1, uint32_t a2, uint32_t a3,
                       uint32_t b0, uint32_t b1) {
  asm("mma.sync.aligned.m16n8k32.row.col.s32.s8.s8.s32 "
      "{%0,%1,%2,%3}, {%4,%5,%6,%7}, {%8,%9}, {%0,%1,%2,%3};"
      : "+r"(c0), "+r"(c1), "+r"(c2), "+r"(c3)
      : "r"(a0), "r"(a1), "r"(a2), "r"(a3), "r"(b0), "r"(b1));
}

// ============================ pre-pass kernels ============================

__global__ void __launch_bounds__(256) k_maxabs(const float4* __restrict__ x) {
  const int n4 = M * K / 4;
  float m = 0.0f;
  for (int i = blockIdx.x * blockDim.x + threadIdx.x; i < n4;
       i += gridDim.x * blockDim.x) {
    float4 v = x[i];
    m = fmaxf(m, fmaxf(fmaxf(fabsf(v.x), fabsf(v.y)),
                       fmaxf(fabsf(v.z), fabsf(v.w))));
  }
  #pragma unroll
  for (int o = 16; o > 0; o >>= 1) m = fmaxf(m, __shfl_xor_sync(0xFFFFFFFFu, m, o));
  __shared__ float red[8];
  if ((threadIdx.x & 31) == 0) red[threadIdx.x >> 5] = m;
  __syncthreads();
  if (threadIdx.x == 0) {
    float t = red[0];
    #pragma unroll
    for (int j = 1; j < 8; ++j) t = fmaxf(t, red[j]);
    g_partial[blockIdx.x] = t;
  }
}

__global__ void __launch_bounds__(256) k_quant(const float4* __restrict__ x) {
  __shared__ float red[8];
  __shared__ float bcast;
  {
    float m = 0.0f;
    #pragma unroll
    for (int j = 0; j < MAX_BLOCKS / 256; ++j)
      m = fmaxf(m, g_partial[threadIdx.x + j * 256]);
    #pragma unroll
    for (int o = 16; o > 0; o >>= 1)
      m = fmaxf(m, __shfl_xor_sync(0xFFFFFFFFu, m, o));
    if ((threadIdx.x & 31) == 0) red[threadIdx.x >> 5] = m;
    __syncthreads();
    if (threadIdx.x == 0) {
      float t = red[0];
      #pragma unroll
      for (int j = 1; j < 8; ++j) t = fmaxf(t, red[j]);
      bcast = t;
      if (blockIdx.x == 0) g_scale = t * (1.0f / 128.0f);
    }
    __syncthreads();
  }
  const float scale = bcast * (1.0f / 128.0f);
  const int n4 = M * K / 4;
  char4* __restrict__ out = (char4*)g_xq;
  for (int i = blockIdx.x * blockDim.x + threadIdx.x; i < n4;
       i += gridDim.x * blockDim.x) {
    float4 v = x[i];
    int a = __float2int_rn(__fdiv_rn(v.x, scale));
    int b = __float2int_rn(__fdiv_rn(v.y, scale));
    int c = __float2int_rn(__fdiv_rn(v.z, scale));
    int d = __float2int_rn(__fdiv_rn(v.w, scale));
    a = max(-128, min(127, a)); b = max(-128, min(127, b));
    c = max(-128, min(127, c)); d = max(-128, min(127, d));
    out[i] = make_char4((signed char)a, (signed char)b,
                        (signed char)c, (signed char)d);
  }
}

// W arrives as INT32 [K][N]; narrow to s8 and transpose to Wt[N][K].
__global__ void __launch_bounds__(256) k_transpose(const int4* __restrict__ W32) {
  __shared__ int8_t tile[64][68];
  const int k0 = blockIdx.x * 64;
  const int n0 = blockIdx.y * 64;
  const int t = threadIdx.x;
  const int Nv = N / 4;

  #pragma unroll
  for (int it = 0; it < 4; ++it) {
    int idx = t + it * 256;
    int r = idx >> 4;
    int cv = idx & 15;
    int4 v = W32[(size_t)(k0 + r) * Nv + (n0 >> 2) + cv];
    uint32_t w = (uint32_t)(uint8_t)(int8_t)v.x
               | ((uint32_t)(uint8_t)(int8_t)v.y << 8)
               | ((uint32_t)(uint8_t)(int8_t)v.z << 16)
               | ((uint32_t)(uint8_t)(int8_t)v.w << 24);
    *(uint32_t*)&tile[r][cv * 4] = w;
  }
  __syncthreads();

  #pragma unroll
  for (int it = 0; it < 4; ++it) {
    int idx = t + it * 256;
    int n = idx >> 4;
    int kk = (idx & 15) << 2;
    uint32_t w = (uint32_t)(uint8_t)tile[kk + 0][n]
               | ((uint32_t)(uint8_t)tile[kk + 1][n] << 8)
               | ((uint32_t)(uint8_t)tile[kk + 2][n] << 16)
               | ((uint32_t)(uint8_t)tile[kk + 3][n] << 24);
    *(uint32_t*)(g_wt + (size_t)(n0 + n) * K + k0 + kk) = w;
  }
}

// ============================ GEMM kernel ============================
// 512 threads, 16 warps: wm = wid&1 (2 along m), wn = wid>>1 (8 along n).
// Warp tile 64x32. BK=128 per stage -> 4 k32-steps per barrier.

DEV_INLINE void load_stage(uint32_t stA, int m0, int n0, int k0, int tid) {
  const uint32_t stB = stA + A_TILE;
  // A: 128 rows x 128B = 1024 cp16; 512 threads -> 2 each
  #pragma unroll
  for (int p = 0; p < 2; ++p) {
    int t2 = tid + p * 512;
    int row = t2 >> 3;
    int ch = (t2 & 7) << 4;
    cp16(stA + row * ASTR + ch, g_xq + (size_t)(m0 + row) * K + k0 + ch);
  }
  // B: 256 rows x 128B = 2048 cp16; 4 each
  #pragma unroll
  for (int p = 0; p < 4; ++p) {
    int t2 = tid + p * 512;
    int row = t2 >> 3;
    int ch = (t2 & 7) << 4;
    cp16(stB + row * ASTR + ch, g_wt + (size_t)(n0 + row) * K + k0 + ch);
  }
}

__global__ void __launch_bounds__(512, 1)
qlinear_gemm(const float* __restrict__ bias, float* __restrict__ out) {
  extern __shared__ __align__(16) char smem[];
  const uint32_t sbase = smem_u32(smem);
  const int tid = threadIdx.x;
  const int wid = tid >> 5;
  const int lane = tid & 31;
  const int wm = wid & 1;        // 2 warps along m
  const int wn = wid >> 1;       // 8 warps along n
  const int m0 = blockIdx.x * BM;
  const int n0 = blockIdx.y * BN;

  // ldmatrix lane roles (mapping proven by R7/R8 identical-output evidence)
  const int row_in = lane & 7;
  const int b = lane >> 3;
  const int a_row = wm * 64 + (b & 1) * 8 + row_in;   // + mt*16
  const int a_coff = (b >> 1) * 16;                   // + kb
  const int b_row = wn * 32 + (b >> 1) * 8 + row_in;  // + p*16
  const int b_coff = (b & 1) * 16;                    // + kb

  int c[4][4][4];
  #pragma unroll
  for (int i = 0; i < 4; ++i)
    #pragma unroll
    for (int j = 0; j < 4; ++j)
      #pragma unroll
      for (int q = 0; q < 4; ++q) c[i][j][q] = 0;

  // prologue: stages 0..1
  #pragma unroll
  for (int j = 0; j < STAGES - 1; ++j) {
    load_stage(sbase + j * STAGE_BYTES, m0, n0, j * BK, tid);
    CP_COMMIT();
  }

  for (int i = 0; i < K_ITERS; ++i) {
    CP_WAIT_1();               // stage i resident (this thread's copies)
    __syncthreads();           // all threads' copies visible
    const uint32_t stA = sbase + (i % STAGES) * STAGE_BYTES;
    const uint32_t stB = stA + A_TILE;

    #pragma unroll
    for (int s = 0; s < 4; ++s) {            // four k32 steps per stage
      const int kb = s * 32;
      uint32_t a[4][4], bb[4][2];
      #pragma unroll
      for (int mt = 0; mt < 4; ++mt)
        ldsm_x4(a[mt][0], a[mt][1], a[mt][2], a[mt][3],
                stA + (a_row + mt * 16) * ASTR + kb + a_coff);
      #pragma unroll
      for (int p = 0; p < 2; ++p) {          // each x4 covers 2 n-tiles
        uint32_t r0, r1, r2, r3;
        ldsm_x4(r0, r1, r2, r3,
                stB + (b_row + p * 16) * ASTR + kb + b_coff);
        bb[2 * p][0] = r0; bb[2 * p][1] = r1;
        bb[2 * p + 1][0] = r2; bb[2 * p + 1][1] = r3;
      }
      #pragma unroll
      for (int mt = 0; mt < 4; ++mt)
        #pragma unroll
        for (int nt = 0; nt < 4; ++nt)
          mma_s8(c[mt][nt][0], c[mt][nt][1], c[mt][nt][2], c[mt][nt][3],
                 a[mt][0], a[mt][1], a[mt][2], a[mt][3],
                 bb[nt][0], bb[nt][1]);
    }

    const int nl = i + STAGES - 1;           // next stage to load
    if (nl < K_ITERS)
      load_stage(sbase + (nl % STAGES) * STAGE_BYTES, m0, n0, nl * BK, tid);
    CP_COMMIT();   // uniform group counting (possibly empty group)
  }

  // epilogue: s32 accum fragment: c0,c1 -> (row g, col tg*2+{0,1});
  // c2,c3 -> row g+8.
  const float s = g_scale * 0.0123f;
  const int gr = lane >> 2;
  const int gc = (lane & 3) << 1;
  #pragma unroll
  for (int mt = 0; mt < 4; ++mt) {
    const int m = m0 + wm * 64 + mt * 16 + gr;
    float* __restrict__ row0 = out + (size_t)m * N;
    float* __restrict__ row1 = row0 + (size_t)8 * N;
    #pragma unroll
    for (int nt = 0; nt < 4; ++nt) {
      const int col = n0 + wn * 32 + nt * 8 + gc;
      const float2 bv = *(const float2*)(bias + col);
      float2 v0, v1;
      v0.x = fmaf((float)c[mt][nt][0], s, bv.x);
      v0.y = fmaf((float)c[mt][nt][1], s, bv.y);
      v1.x = fmaf((float)c[mt][nt][2], s, bv.x);
      v1.y = fmaf((float)c[mt][nt][3], s, bv.y);
      *(float2*)(row0 + col) = v0;
      *(float2*)(row1 + col) = v1;
    }
  }
}

// ============================ launch ============================

extern "C" void kernel_launch(void* const* d_in, const int* in_sizes, int n_in,
                              void* d_out, int out_size) {
  const float* x    = (const float*)d_in[0];
  const int*   W32  = (const int*)d_in[1];    // int8 weights promoted to int32
  const float* bias = (const float*)d_in[2];
  float* out = (float*)d_out;

  k_maxabs<<<MAX_BLOCKS, 256>>>((const float4*)x);
  k_quant<<<2048, 256>>>((const float4*)x);
  {
    dim3 tg(K / 64, N / 64);    // 64 x 172
    k_transpose<<<tg, 256>>>((const int4*)W32);
  }

  cudaFuncSetAttribute(qlinear_gemm,
                       cudaFuncAttributeMaxDynamicSharedMemorySize, SMEM_TOTAL);
  dim3 grid(M / BM, N / BN);    // 16 x 43; m fastest -> B-stripe L2 reuse
  qlinear_gemm<<<grid, 512, SMEM_TOTAL>>>(bias, out);
}

// round 12
// speedup vs baseline: 1.2392x; 1.0006x over previous
#include <cuda_runtime.h>
#include <cstdint>

#define DEV_INLINE __device__ __forceinline__

static constexpr int M = 2048, K = 4096, N = 11008;
static constexpr int BM = 128, BN = 256, BK = 128;
static constexpr int STAGES = 3;
static constexpr int K_ITERS = K / BK;              // 32
static constexpr int ASTR = 144;                    // 128B row + 16B pad (conflict-free)
static constexpr int A_TILE = BM * ASTR;            // 18432
static constexpr int B_TILE = BN * ASTR;            // 36864
static constexpr int STAGE_BYTES = A_TILE + B_TILE; // 55296
static constexpr int SMEM_TOTAL = STAGES * STAGE_BYTES;  // 165888
static constexpr int MAX_BLOCKS = 1024;

__device__ int8_t g_xq[(size_t)M * K];      // quantized activations
__device__ int8_t g_wt[(size_t)N * K];      // W narrowed + transposed to [N, K] s8
__device__ float g_partial[MAX_BLOCKS];     // per-block |x| maxima
__device__ float g_scale;                   // max|x| / 128

// ============================ PTX helpers ============================

DEV_INLINE uint32_t smem_u32(const void* p) {
  uint32_t a;
  asm("{ .reg .u64 t; cvta.to.shared.u64 t, %1; cvt.u32.u64 %0, t; }"
      : "=r"(a) : "l"(p));
  return a;
}

DEV_INLINE void cp16(uint32_t dst, const void* src) {
  asm volatile("cp.async.cg.shared.global [%0], [%1], 16;"
               :: "r"(dst), "l"(src));
}
#define CP_COMMIT() asm volatile("cp.async.commit_group;" ::: "memory")
#define CP_WAIT_1() asm volatile("cp.async.wait_group 1;" ::: "memory")

// Non-volatile: lets ptxas software-pipeline ldsm across mma phases.
// Safety proven by R7/R8 identical-output evidence.
DEV_INLINE void ldsm_x4(uint32_t& r0, uint32_t& r1, uint32_t& r2, uint32_t& r3,
                        uint32_t addr) {
  asm("ldmatrix.sync.aligned.m8n8.x4.shared.b16 {%0,%1,%2,%3}, [%4];"
      : "=r"(r0), "=r"(r1), "=r"(r2), "=r"(r3) : "r"(addr));
}

DEV_INLINE void mma_s8(int& c0, int& c1, int& c2, int& c3,
                       uint32_t a0, uint32_t a1, uint32_t a2, uint32_t a3,
                       uint32_t b0, uint32_t b1) {
  asm("mma.sync.aligned.m16n8k32.row.col.s32.s8.s8.s32 "
      "{%0,%1,%2,%3}, {%4,%5,%6,%7}, {%8,%9}, {%0,%1,%2,%3};"
      : "+r"(c0), "+r"(c1), "+r"(c2), "+r"(c3)
      : "r"(a0), "r"(a1), "r"(a2), "r"(a3), "r"(b0), "r"(b1));
}

// ============================ pre-pass kernels ============================

__global__ void __launch_bounds__(256) k_maxabs(const float4* __restrict__ x) {
  const int n4 = M * K / 4;
  float m = 0.0f;
  for (int i = blockIdx.x * blockDim.x + threadIdx.x; i < n4;
       i += gridDim.x * blockDim.x) {
    float4 v = x[i];
    m = fmaxf(m, fmaxf(fmaxf(fabsf(v.x), fabsf(v.y)),
                       fmaxf(fabsf(v.z), fabsf(v.w))));
  }
  #pragma unroll
  for (int o = 16; o > 0; o >>= 1) m = fmaxf(m, __shfl_xor_sync(0xFFFFFFFFu, m, o));
  __shared__ float red[8];
  if ((threadIdx.x & 31) == 0) red[threadIdx.x >> 5] = m;
  __syncthreads();
  if (threadIdx.x == 0) {
    float t = red[0];
    #pragma unroll
    for (int j = 1; j < 8; ++j) t = fmaxf(t, red[j]);
    g_partial[blockIdx.x] = t;
  }
}

__global__ void __launch_bounds__(256) k_quant(const float4* __restrict__ x) {
  __shared__ float red[8];
  __shared__ float bcast;
  {
    float m = 0.0f;
    #pragma unroll
    for (int j = 0; j < MAX_BLOCKS / 256; ++j)
      m = fmaxf(m, g_partial[threadIdx.x + j * 256]);
    #pragma unroll
    for (int o = 16; o > 0; o >>= 1)
      m = fmaxf(m, __shfl_xor_sync(0xFFFFFFFFu, m, o));
    if ((threadIdx.x & 31) == 0) red[threadIdx.x >> 5] = m;
    __syncthreads();
    if (threadIdx.x == 0) {
      float t = red[0];
      #pragma unroll
      for (int j = 1; j < 8; ++j) t = fmaxf(t, red[j]);
      bcast = t;
      if (blockIdx.x == 0) g_scale = t * (1.0f / 128.0f);
    }
    __syncthreads();
  }
  const float scale = bcast * (1.0f / 128.0f);
  const int n4 = M * K / 4;
  char4* __restrict__ out = (char4*)g_xq;
  for (int i = blockIdx.x * blockDim.x + threadIdx.x; i < n4;
       i += gridDim.x * blockDim.x) {
    float4 v = x[i];
    int a = __float2int_rn(__fdiv_rn(v.x, scale));
    int b = __float2int_rn(__fdiv_rn(v.y, scale));
    int c = __float2int_rn(__fdiv_rn(v.z, scale));
    int d = __float2int_rn(__fdiv_rn(v.w, scale));
    a = max(-128, min(127, a)); b = max(-128, min(127, b));
    c = max(-128, min(127, c)); d = max(-128, min(127, d));
    out[i] = make_char4((signed char)a, (signed char)b,
                        (signed char)c, (signed char)d);
  }
}

// W arrives as INT32 [K][N]; narrow to s8 and transpose to Wt[N][K].
__global__ void __launch_bounds__(256) k_transpose(const int4* __restrict__ W32) {
  __shared__ int8_t tile[64][68];
  const int k0 = blockIdx.x * 64;
  const int n0 = blockIdx.y * 64;
  const int t = threadIdx.x;
  const int Nv = N / 4;

  #pragma unroll
  for (int it = 0; it < 4; ++it) {
    int idx = t + it * 256;
    int r = idx >> 4;
    int cv = idx & 15;
    int4 v = W32[(size_t)(k0 + r) * Nv + (n0 >> 2) + cv];
    uint32_t w = (uint32_t)(uint8_t)(int8_t)v.x
               | ((uint32_t)(uint8_t)(int8_t)v.y << 8)
               | ((uint32_t)(uint8_t)(int8_t)v.z << 16)
               | ((uint32_t)(uint8_t)(int8_t)v.w << 24);
    *(uint32_t*)&tile[r][cv * 4] = w;
  }
  __syncthreads();

  #pragma unroll
  for (int it = 0; it < 4; ++it) {
    int idx = t + it * 256;
    int n = idx >> 4;
    int kk = (idx & 15) << 2;
    uint32_t w = (uint32_t)(uint8_t)tile[kk + 0][n]
               | ((uint32_t)(uint8_t)tile[kk + 1][n] << 8)
               | ((uint32_t)(uint8_t)tile[kk + 2][n] << 16)
               | ((uint32_t)(uint8_t)tile[kk + 3][n] << 24);
    *(uint32_t*)(g_wt + (size_t)(n0 + n) * K + k0 + kk) = w;
  }
}

// ============================ GEMM kernel ============================
// 256 threads, 8 warps: wm = wid&1 (2 along m), wn = wid>>1 (4 along n).
// Warp tile 64x64 (CUTLASS int8 shape). BK=128 -> 4 k32-steps per barrier.
// 255-reg budget gives ptxas room to pipeline ldsm ahead of mma.

DEV_INLINE void load_stage(uint32_t stA, int m0, int n0, int k0, int tid) {
  const uint32_t stB = stA + A_TILE;
  // A: 128 rows x 8 chunks = 1024 cp16; 256 threads -> 4 each
  #pragma unroll
  for (int p = 0; p < 4; ++p) {
    int t2 = tid + p * 256;
    int row = t2 >> 3;
    int ch = (t2 & 7) << 4;
    cp16(stA + row * ASTR + ch, g_xq + (size_t)(m0 + row) * K + k0 + ch);
  }
  // B: 256 rows x 8 chunks = 2048 cp16; 8 each
  #pragma unroll
  for (int p = 0; p < 8; ++p) {
    int t2 = tid + p * 256;
    int row = t2 >> 3;
    int ch = (t2 & 7) << 4;
    cp16(stB + row * ASTR + ch, g_wt + (size_t)(n0 + row) * K + k0 + ch);
  }
}

__global__ void __launch_bounds__(256, 1)
qlinear_gemm(const float* __restrict__ bias, float* __restrict__ out) {
  extern __shared__ __align__(16) char smem[];
  const uint32_t sbase = smem_u32(smem);
  const int tid = threadIdx.x;
  const int wid = tid >> 5;
  const int lane = tid & 31;
  const int wm = wid & 1;        // 2 warps along m
  const int wn = wid >> 1;       // 4 warps along n
  const int m0 = blockIdx.x * BM;
  const int n0 = blockIdx.y * BN;

  // ldmatrix lane roles (mapping proven by R7/R8 identical-output evidence)
  const int row_in = lane & 7;
  const int b = lane >> 3;
  const int a_row = wm * 64 + (b & 1) * 8 + row_in;   // + mt*16
  const int a_coff = (b >> 1) * 16;                   // + kb
  const int b_row = wn * 64 + (b >> 1) * 8 + row_in;  // + p*16
  const int b_coff = (b & 1) * 16;                    // + kb

  int c[4][8][4];
  #pragma unroll
  for (int i = 0; i < 4; ++i)
    #pragma unroll
    for (int j = 0; j < 8; ++j)
      #pragma unroll
      for (int q = 0; q < 4; ++q) c[i][j][q] = 0;

  // prologue: stages 0..1
  #pragma unroll
  for (int j = 0; j < STAGES - 1; ++j) {
    load_stage(sbase + j * STAGE_BYTES, m0, n0, j * BK, tid);
    CP_COMMIT();
  }

  for (int i = 0; i < K_ITERS; ++i) {
    CP_WAIT_1();               // stage i resident (this thread's copies)
    __syncthreads();           // all threads' copies visible
    const uint32_t stA = sbase + (i % STAGES) * STAGE_BYTES;
    const uint32_t stB = stA + A_TILE;
    const int nl = i + STAGES - 1;           // next stage to load

    #pragma unroll
    for (int s = 0; s < 4; ++s) {            // four k32 steps per stage
      const int kb = s * 32;
      uint32_t a[4][4], bb[8][2];
      #pragma unroll
      for (int mt = 0; mt < 4; ++mt)
        ldsm_x4(a[mt][0], a[mt][1], a[mt][2], a[mt][3],
                stA + (a_row + mt * 16) * ASTR + kb + a_coff);
      #pragma unroll
      for (int p = 0; p < 4; ++p) {          // each x4 covers 2 n-tiles
        uint32_t r0, r1, r2, r3;
        ldsm_x4(r0, r1, r2, r3,
                stB + (b_row + p * 16) * ASTR + kb + b_coff);
        bb[2 * p][0] = r0; bb[2 * p][1] = r1;
        bb[2 * p + 1][0] = r2; bb[2 * p + 1][1] = r3;
      }
      #pragma unroll
      for (int mt = 0; mt < 4; ++mt)
        #pragma unroll
        for (int nt = 0; nt < 8; ++nt)
          mma_s8(c[mt][nt][0], c[mt][nt][1], c[mt][nt][2], c[mt][nt][3],
                 a[mt][0], a[mt][1], a[mt][2], a[mt][3],
                 bb[nt][0], bb[nt][1]);
      // overlap next-stage cp.async with remaining k-steps
      if (s == 0 && nl < K_ITERS)
        load_stage(sbase + (nl % STAGES) * STAGE_BYTES, m0, n0, nl * BK, tid);
    }
    CP_COMMIT();   // uniform group counting (possibly empty group)
  }

  // epilogue: s32 accum fragment: c0,c1 -> (row g, col tg*2+{0,1});
  // c2,c3 -> row g+8.
  const float s = g_scale * 0.0123f;
  const int gr = lane >> 2;
  const int gc = (lane & 3) << 1;
  #pragma unroll
  for (int mt = 0; mt < 4; ++mt) {
    const int m = m0 + wm * 64 + mt * 16 + gr;
    float* __restrict__ row0 = out + (size_t)m * N;
    float* __restrict__ row1 = row0 + (size_t)8 * N;
    #pragma unroll
    for (int nt = 0; nt < 8; ++nt) {
      const int col = n0 + wn * 64 + nt * 8 + gc;
      const float2 bv = *(const float2*)(bias + col);
      float2 v0, v1;
      v0.x = fmaf((float)c[mt][nt][0], s, bv.x);
      v0.y = fmaf((float)c[mt][nt][1], s, bv.y);
      v1.x = fmaf((float)c[mt][nt][2], s, bv.x);
      v1.y = fmaf((float)c[mt][nt][3], s, bv.y);
      *(float2*)(row0 + col) = v0;
      *(float2*)(row1 + col) = v1;
    }
  }
}

// ============================ launch ============================

extern "C" void kernel_launch(void* const* d_in, const int* in_sizes, int n_in,
                              void* d_out, int out_size) {
  const float* x    = (const float*)d_in[0];
  const int*   W32  = (const int*)d_in[1];    // int8 weights promoted to int32
  const float* bias = (const float*)d_in[2];
  float* out = (float*)d_out;

  k_maxabs<<<MAX_BLOCKS, 256>>>((const float4*)x);
  k_quant<<<2048, 256>>>((const float4*)x);
  {
    dim3 tg(K / 64, N / 64);    // 64 x 172
    k_transpose<<<tg, 256>>>((const int4*)W32);
  }

  cudaFuncSetAttribute(qlinear_gemm,
                       cudaFuncAttributeMaxDynamicSharedMemorySize, SMEM_TOTAL);
  dim3 grid(M / BM, N / BN);    // 16 x 43; m fastest -> B-stripe L2 reuse
  qlinear_gemm<<<grid, 256, SMEM_TOTAL>>>(bias, out);
}